// round 2
// baseline (speedup 1.0000x reference)
#include <cuda_runtime.h>
#include <math.h>

#define Nn   100000
#define Ee   1600000
#define NH   (Nn * 64)
#define NB_SCAN 98   // ceil(100000/1024)

// ---- persistent device scratch (no allocations allowed) ----
__device__ float g_dinv[Nn];
__device__ int   g_cnt[Nn];
__device__ int   g_off[Nn];
__device__ int   g_cur[Nn];
__device__ int   g_bsum[128];
__device__ int2  g_csr[Ee];
__device__ float g_hb[3][NH];
__device__ float g_seq[(size_t)Nn * 256];
__device__ float g_Mt[4096];   // Mt[b*64+a] = sum_j Wq[j][a]*Wk[j][b]
__device__ float g_Wvo[4096];  // Wvo[b*64+a] = sum_j Wout[a][j]*Wv[j][b]
__device__ float g_p2[64];     // p2[b] = sum_j bq[j]*Wk[j][b]
__device__ float g_bvo[64];    // bvo[a] = sum_j Wout[a][j]*bv[j] + bout[a]

// ================= degree / CSR build =================
__global__ void k_init() {
    int i = blockIdx.x * blockDim.x + threadIdx.x;
    if (i < Nn) g_cnt[i] = 0;
}
__global__ void k_count(const int* __restrict__ dst) {
    int e = blockIdx.x * blockDim.x + threadIdx.x;
    if (e < Ee) atomicAdd(&g_cnt[dst[e]], 1);
}
__global__ void k_scan1() {
    __shared__ int smv[1024];
    int i = blockIdx.x * 1024 + threadIdx.x;
    int v = (i < Nn) ? g_cnt[i] : 0;
    smv[threadIdx.x] = v;
    __syncthreads();
    for (int off = 1; off < 1024; off <<= 1) {
        int t = 0;
        if (threadIdx.x >= off) t = smv[threadIdx.x - off];
        __syncthreads();
        if (threadIdx.x >= off) smv[threadIdx.x] += t;
        __syncthreads();
    }
    if (i < Nn) g_off[i] = smv[threadIdx.x];
    if (threadIdx.x == 1023) g_bsum[blockIdx.x] = smv[1023];
}
__global__ void k_scan2() {
    int acc = 0;
    for (int b = 0; b < NB_SCAN; b++) { int t = g_bsum[b]; g_bsum[b] = acc; acc += t; }
}
__global__ void k_scan3() {
    int i = blockIdx.x * 1024 + threadIdx.x;
    if (i < Nn) {
        int incl = g_off[i] + g_bsum[i >> 10];
        int excl = incl - g_cnt[i];
        g_off[i] = excl;
        g_cur[i] = excl;
        g_dinv[i] = rsqrtf((float)g_cnt[i] + 1.0f);
    }
}
__global__ void k_fill(const int* __restrict__ src, const int* __restrict__ dst) {
    int e = blockIdx.x * blockDim.x + threadIdx.x;
    if (e < Ee) {
        int s = src[e], d = dst[e];
        int pos = atomicAdd(&g_cur[d], 1);
        g_csr[pos] = make_int2(s, __float_as_int(g_dinv[s]));
    }
}

// ================= h0 = relu(x @ W_in^T + b_in) =================
// 4 rows per warp, float4 weights (padded rows) + float4 x broadcast.
__global__ void k_in_linear(const float* __restrict__ x, const float* __restrict__ W,
                            const float* __restrict__ b) {
    extern __shared__ float sm[];
    float* Ws = sm;                 // [64][260] (row j of W, padded)
    float* bb = Ws + 64 * 260;      // 64
    float* xb = bb + 64;            // 8 warps * 1024
    int tid = threadIdx.x;
    for (int i = tid; i < 64 * 64; i += 256) {   // float4 granularity
        int j = i >> 6, q = i & 63;
        ((float4*)(Ws + j * 260))[q] = ((const float4*)(W + j * 256))[q];
    }
    if (tid < 64) bb[tid] = b[tid];
    __syncthreads();
    int warp = tid >> 5, l = tid & 31;
    float* xw = xb + warp * 1024;
    const float* w0p = Ws + l * 260;
    const float* w1p = Ws + (l + 32) * 260;
    for (int grp = blockIdx.x * 8 + warp; grp < 25000; grp += gridDim.x * 8) {
        int row0 = grp * 4;
        const float4* xg = (const float4*)(x + (size_t)row0 * 256);
        #pragma unroll
        for (int r = 0; r < 4; r++) {
            ((float4*)xw)[r * 64 + l]      = xg[r * 64 + l];
            ((float4*)xw)[r * 64 + l + 32] = xg[r * 64 + l + 32];
        }
        __syncwarp();
        float acc0[4], acc1[4];
        #pragma unroll
        for (int r = 0; r < 4; r++) { acc0[r] = bb[l]; acc1[r] = bb[l + 32]; }
        #pragma unroll 4
        for (int k4 = 0; k4 < 64; k4++) {
            float4 wa = ((const float4*)w0p)[k4];
            float4 wb = ((const float4*)w1p)[k4];
            #pragma unroll
            for (int r = 0; r < 4; r++) {
                float4 xv = ((const float4*)(xw + r * 256))[k4];
                acc0[r] = fmaf(xv.x, wa.x, acc0[r]);
                acc0[r] = fmaf(xv.y, wa.y, acc0[r]);
                acc0[r] = fmaf(xv.z, wa.z, acc0[r]);
                acc0[r] = fmaf(xv.w, wa.w, acc0[r]);
                acc1[r] = fmaf(xv.x, wb.x, acc1[r]);
                acc1[r] = fmaf(xv.y, wb.y, acc1[r]);
                acc1[r] = fmaf(xv.z, wb.z, acc1[r]);
                acc1[r] = fmaf(xv.w, wb.w, acc1[r]);
            }
        }
        #pragma unroll
        for (int r = 0; r < 4; r++) {
            float a0 = fmaxf(acc0[r], 0.f), a1 = fmaxf(acc1[r], 0.f);
            size_t row = row0 + r;
            g_hb[0][row * 64 + l]      = a0;
            g_hb[0][row * 64 + l + 32] = a1;
            g_seq[row * 256 + l]       = a0;
            g_seq[row * 256 + l + 32]  = a1;
        }
        __syncwarp();
    }
}

// ================= fused gather-propagate + token linear =================
// warp per node: p = dinv[n] * (sum_in dinv[s]*h[s] + dinv[n]*h[n]);
// token = relu(p @ sgW^T + sgb) into seq slot.
__global__ void k_prop(int inb, int outb, const float* __restrict__ W,
                       const float* __restrict__ b, int slot) {
    __shared__ float Wt[4096];    // Wt[k*64+j] = W[j*64+k]
    __shared__ float bb[64];
    __shared__ float pbuf[8 * 64];
    int tid = threadIdx.x;
    for (int i = tid; i < 4096; i += 256) {
        int k = i >> 6, j = i & 63;
        Wt[i] = W[j * 64 + k];
    }
    if (tid < 64) bb[tid] = b[tid];
    __syncthreads();
    int warp = tid >> 5, l = tid & 31;
    float* pw = pbuf + warp * 64;
    const float* hin = g_hb[inb];
    float* hout = g_hb[outb];
    for (int n = blockIdx.x * 8 + warp; n < Nn; n += gridDim.x * 8) {
        int beg = g_off[n], cnt = g_cnt[n];
        float dn = g_dinv[n];
        float2 hv = *((const float2*)(hin + (size_t)n * 64) + l);
        float a0 = dn * hv.x, a1 = dn * hv.y;
        int i = 0;
        for (; i + 2 <= cnt; i += 2) {
            int2 e0 = __ldg(g_csr + beg + i);
            int2 e1 = __ldg(g_csr + beg + i + 1);
            float2 v0 = __ldg((const float2*)(hin + (size_t)e0.x * 64) + l);
            float2 v1 = __ldg((const float2*)(hin + (size_t)e1.x * 64) + l);
            float w0 = __int_as_float(e0.y), w1 = __int_as_float(e1.y);
            a0 = fmaf(w0, v0.x, a0); a1 = fmaf(w0, v0.y, a1);
            a0 = fmaf(w1, v1.x, a0); a1 = fmaf(w1, v1.y, a1);
        }
        if (i < cnt) {
            int2 e0 = __ldg(g_csr + beg + i);
            float2 v0 = __ldg((const float2*)(hin + (size_t)e0.x * 64) + l);
            float w0 = __int_as_float(e0.y);
            a0 = fmaf(w0, v0.x, a0); a1 = fmaf(w0, v0.y, a1);
        }
        a0 *= dn; a1 *= dn;
        *((float2*)(hout + (size_t)n * 64) + l) = make_float2(a0, a1);
        *((float2*)pw + l) = make_float2(a0, a1);
        __syncwarp();
        // token GEMV
        float t0 = bb[l], t1 = bb[l + 32];
        #pragma unroll 4
        for (int k4 = 0; k4 < 16; k4++) {
            float4 xv = ((const float4*)pw)[k4];
            const float* wr = Wt + k4 * 256;
            t0 = fmaf(xv.x, wr[l], t0);        t1 = fmaf(xv.x, wr[l + 32], t1);
            t0 = fmaf(xv.y, wr[64 + l], t0);   t1 = fmaf(xv.y, wr[96 + l], t1);
            t0 = fmaf(xv.z, wr[128 + l], t0);  t1 = fmaf(xv.z, wr[160 + l], t1);
            t0 = fmaf(xv.w, wr[192 + l], t0);  t1 = fmaf(xv.w, wr[224 + l], t1);
        }
        float* op = g_seq + (size_t)n * 256 + slot * 64;
        op[l]      = fmaxf(t0, 0.f);
        op[l + 32] = fmaxf(t1, 0.f);
        __syncwarp();
    }
}

// ================= precompute folded attention matrices =================
__global__ void k_pre(const float* __restrict__ inW, const float* __restrict__ inb,
                      const float* __restrict__ WoutG, const float* __restrict__ boutG) {
    int e = blockIdx.x * blockDim.x + threadIdx.x;
    if (e < 4096) {
        int bcol = e >> 6, a = e & 63;
        float m = 0.f, wv = 0.f;
        for (int j = 0; j < 64; j++) {
            m  = fmaf(__ldg(inW + j * 64 + a),  __ldg(inW + (64 + j) * 64 + bcol), m);
            wv = fmaf(__ldg(WoutG + a * 64 + j), __ldg(inW + (128 + j) * 64 + bcol), wv);
        }
        g_Mt[e] = m;        // Mt[b*64+a]
        g_Wvo[e] = wv;      // Wvo[b*64+a]
    }
    if (e < 64) {
        float p = 0.f;
        for (int j = 0; j < 64; j++) p = fmaf(__ldg(inb + j), __ldg(inW + (64 + j) * 64 + e), p);
        g_p2[e] = p;
    } else if (e < 128) {
        int a = e - 64;
        float bv = __ldg(boutG + a);
        for (int j = 0; j < 64; j++) bv = fmaf(__ldg(WoutG + a * 64 + j), __ldg(inb + 128 + j), bv);
        g_bvo[a] = bv;
    }
}

// ================= fused transformer + mean + classifier =================
// 16 warps/CTA, 1 warp per node. Lane: t = l>>3 (token), g = l&7.
__global__ void __launch_bounds__(512, 1) k_former(
    const float* __restrict__ W1_g, const float* __restrict__ b1_g,
    const float* __restrict__ W2_g, const float* __restrict__ b2_g,
    const float* __restrict__ ln1w_g, const float* __restrict__ ln1b_g,
    const float* __restrict__ ln2w_g, const float* __restrict__ ln2b_g,
    const float* __restrict__ Wcls_g, const float* __restrict__ bcls_g,
    float* __restrict__ out)
{
    extern __shared__ float sm[];
    float* MtS   = sm;              // [64][68]
    float* WvoS  = MtS + 4352;      // [64][68]
    float* W1S   = WvoS + 4352;     // [64][132]
    float* W2S   = W1S + 8448;      // [128][68]
    float* WclsS = W2S + 8704;      // [64][40]
    float* p2S   = WclsS + 2560;
    float* bvoS  = p2S + 64;
    float* b1S   = bvoS + 64;
    float* b2S   = b1S + 128;
    float* bclsS = b2S + 64;
    float* ln1wS = bclsS + 40;
    float* ln1bS = ln1wS + 64;
    float* ln2wS = ln1bS + 64;
    float* ln2bS = ln2wS + 64;
    float* scratch = ln2bS + 64;    // 16 warps * 1104

    int tid = threadIdx.x;
    for (int i = tid; i < 4096; i += 512) {
        int bc = i >> 6, a = i & 63;
        MtS[bc * 68 + a]  = g_Mt[i];
        WvoS[bc * 68 + a] = g_Wvo[i];
    }
    for (int i = tid; i < 8192; i += 512) { int j = i & 127, k = i >> 7; W1S[k * 132 + j] = W1_g[j * 64 + k]; }
    for (int i = tid; i < 8192; i += 512) { int j = i & 63,  k = i >> 6; W2S[k * 68 + j]  = W2_g[j * 128 + k]; }
    for (int i = tid; i < 2560; i += 512) { int j = i % 40,  k = i / 40; WclsS[k * 40 + j] = Wcls_g[j * 64 + k]; }
    if (tid < 64) {
        p2S[tid] = g_p2[tid]; bvoS[tid] = g_bvo[tid]; b2S[tid] = b2_g[tid];
        ln1wS[tid] = ln1w_g[tid]; ln1bS[tid] = ln1b_g[tid];
        ln2wS[tid] = ln2w_g[tid]; ln2bS[tid] = ln2b_g[tid];
    }
    if (tid < 128) b1S[tid] = b1_g[tid];
    if (tid < 40) bclsS[tid] = bcls_g[tid];
    __syncthreads();

    int warp = tid >> 5, l = tid & 31;
    float* s   = scratch + warp * 1104;  // 256
    float* z   = s + 256;                // 256
    float* b2f = z + 256;                // 512
    float* sc  = b2f + 512;              // 16
    float* hb  = sc + 16;                // 64
    const int t = l >> 3, g = l & 7;
    float* srow = s + t * 64;

    for (int n = blockIdx.x * 16 + warp; n < Nn; n += gridDim.x * 16) {
        const float4* sp = (const float4*)(g_seq + (size_t)n * 256);
        ((float4*)s)[l]      = sp[l];
        ((float4*)s)[l + 32] = sp[l + 32];
        __syncwarp();

        // ---- z_t = M seq_t ----
        {
            float acc[8];
            #pragma unroll
            for (int i = 0; i < 8; i++) acc[i] = 0.f;
            for (int k4 = 0; k4 < 16; k4++) {
                float4 xv = ((const float4*)srow)[k4];
                #pragma unroll
                for (int kk = 0; kk < 4; kk++) {
                    const float4* wr = (const float4*)(MtS + (k4 * 4 + kk) * 68 + g * 8);
                    float4 wA = wr[0], wB = wr[1];
                    float xk = kk == 0 ? xv.x : kk == 1 ? xv.y : kk == 2 ? xv.z : xv.w;
                    acc[0] = fmaf(xk, wA.x, acc[0]); acc[1] = fmaf(xk, wA.y, acc[1]);
                    acc[2] = fmaf(xk, wA.z, acc[2]); acc[3] = fmaf(xk, wA.w, acc[3]);
                    acc[4] = fmaf(xk, wB.x, acc[4]); acc[5] = fmaf(xk, wB.y, acc[5]);
                    acc[6] = fmaf(xk, wB.z, acc[6]); acc[7] = fmaf(xk, wB.w, acc[7]);
                }
            }
            float* zp = z + t * 64 + g * 8;
            ((float4*)zp)[0] = make_float4(acc[0], acc[1], acc[2], acc[3]);
            ((float4*)zp)[1] = make_float4(acc[4], acc[5], acc[6], acc[7]);
        }
        __syncwarp();

        // ---- scores + softmax (bias terms constant per row dropped) ----
        if (l < 16) {
            int ss = l >> 2, tt = l & 3;
            const float4* ap = (const float4*)(s + ss * 64);
            const float4* zp = (const float4*)(z + tt * 64);
            const float4* bp = (const float4*)(s + tt * 64);
            const float4* pp = (const float4*)p2S;
            float d = 0.f;
            #pragma unroll 4
            for (int k4 = 0; k4 < 16; k4++) {
                float4 a = ap[k4], zz = zp[k4], bq = bp[k4], p = pp[k4];
                d += a.x * zz.x + a.y * zz.y + a.z * zz.z + a.w * zz.w;
                d += p.x * bq.x + p.y * bq.y + p.z * bq.z + p.w * bq.w;
            }
            sc[l] = d * 0.125f;
        }
        __syncwarp();
        if (l < 4) {
            float s0 = sc[l*4], s1 = sc[l*4+1], s2 = sc[l*4+2], s3 = sc[l*4+3];
            float m = fmaxf(fmaxf(s0, s1), fmaxf(s2, s3));
            float e0 = __expf(s0 - m), e1 = __expf(s1 - m), e2 = __expf(s2 - m), e3 = __expf(s3 - m);
            float inv = 1.f / (e0 + e1 + e2 + e3);
            sc[l*4] = e0*inv; sc[l*4+1] = e1*inv; sc[l*4+2] = e2*inv; sc[l*4+3] = e3*inv;
        }
        __syncwarp();

        // ---- m_t = sum_c P[t,c] seq_c ----
        {
            float w0 = sc[t*4], w1 = sc[t*4+1], w2 = sc[t*4+2], w3 = sc[t*4+3];
            #pragma unroll
            for (int c = 0; c < 2; c++) {
                int q = g * 2 + c;
                float4 s0 = ((const float4*)s)[q];
                float4 s1 = ((const float4*)(s + 64))[q];
                float4 s2 = ((const float4*)(s + 128))[q];
                float4 s3 = ((const float4*)(s + 192))[q];
                float4 r;
                r.x = w0*s0.x + w1*s1.x + w2*s2.x + w3*s3.x;
                r.y = w0*s0.y + w1*s1.y + w2*s2.y + w3*s3.y;
                r.z = w0*s0.z + w1*s1.z + w2*s2.z + w3*s3.z;
                r.w = w0*s0.w + w1*s1.w + w2*s2.w + w3*s3.w;
                ((float4*)(b2f + t * 64))[q] = r;
            }
        }
        __syncwarp();

        // ---- out = Wvo m + bvo, residual, LN1 ----
        {
            float r[8];
            #pragma unroll
            for (int i = 0; i < 8; i++) r[i] = bvoS[g * 8 + i];
            const float* arow = b2f + t * 64;
            for (int k4 = 0; k4 < 16; k4++) {
                float4 av = ((const float4*)arow)[k4];
                #pragma unroll
                for (int kk = 0; kk < 4; kk++) {
                    const float4* wr = (const float4*)(WvoS + (k4 * 4 + kk) * 68 + g * 8);
                    float4 wA = wr[0], wB = wr[1];
                    float ak = kk == 0 ? av.x : kk == 1 ? av.y : kk == 2 ? av.z : av.w;
                    r[0] = fmaf(ak, wA.x, r[0]); r[1] = fmaf(ak, wA.y, r[1]);
                    r[2] = fmaf(ak, wA.z, r[2]); r[3] = fmaf(ak, wA.w, r[3]);
                    r[4] = fmaf(ak, wB.x, r[4]); r[5] = fmaf(ak, wB.y, r[5]);
                    r[6] = fmaf(ak, wB.z, r[6]); r[7] = fmaf(ak, wB.w, r[7]);
                }
            }
            float4 rs0 = ((const float4*)srow)[g*2], rs1 = ((const float4*)srow)[g*2+1];
            r[0] += rs0.x; r[1] += rs0.y; r[2] += rs0.z; r[3] += rs0.w;
            r[4] += rs1.x; r[5] += rs1.y; r[6] += rs1.z; r[7] += rs1.w;
            float sum = 0.f;
            #pragma unroll
            for (int i = 0; i < 8; i++) sum += r[i];
            sum += __shfl_xor_sync(0xffffffffu, sum, 1);
            sum += __shfl_xor_sync(0xffffffffu, sum, 2);
            sum += __shfl_xor_sync(0xffffffffu, sum, 4);
            float mean = sum * 0.015625f;
            float sq = 0.f;
            #pragma unroll
            for (int i = 0; i < 8; i++) { float dd = r[i] - mean; sq = fmaf(dd, dd, sq); }
            sq += __shfl_xor_sync(0xffffffffu, sq, 1);
            sq += __shfl_xor_sync(0xffffffffu, sq, 2);
            sq += __shfl_xor_sync(0xffffffffu, sq, 4);
            float inv = rsqrtf(sq * 0.015625f + 1e-5f);
            float4 w0v = ((const float4*)ln1wS)[g*2], w1v = ((const float4*)ln1wS)[g*2+1];
            float4 b0v = ((const float4*)ln1bS)[g*2], b1v = ((const float4*)ln1bS)[g*2+1];
            float4 o0, o1;
            o0.x = (r[0]-mean)*inv*w0v.x + b0v.x; o0.y = (r[1]-mean)*inv*w0v.y + b0v.y;
            o0.z = (r[2]-mean)*inv*w0v.z + b0v.z; o0.w = (r[3]-mean)*inv*w0v.w + b0v.w;
            o1.x = (r[4]-mean)*inv*w1v.x + b1v.x; o1.y = (r[5]-mean)*inv*w1v.y + b1v.y;
            o1.z = (r[6]-mean)*inv*w1v.z + b1v.z; o1.w = (r[7]-mean)*inv*w1v.w + b1v.w;
            ((float4*)srow)[g*2] = o0; ((float4*)srow)[g*2+1] = o1;
        }
        __syncwarp();

        // ---- FF1 + exact gelu ----
        {
            float ga[16];
            #pragma unroll
            for (int i = 0; i < 16; i++) ga[i] = b1S[g * 16 + i];
            for (int k4 = 0; k4 < 16; k4++) {
                float4 xv = ((const float4*)srow)[k4];
                #pragma unroll
                for (int kk = 0; kk < 4; kk++) {
                    const float4* wr = (const float4*)(W1S + (k4 * 4 + kk) * 132 + g * 16);
                    float4 wA = wr[0], wB = wr[1], wC = wr[2], wD = wr[3];
                    float xk = kk == 0 ? xv.x : kk == 1 ? xv.y : kk == 2 ? xv.z : xv.w;
                    ga[0]  = fmaf(xk, wA.x, ga[0]);  ga[1]  = fmaf(xk, wA.y, ga[1]);
                    ga[2]  = fmaf(xk, wA.z, ga[2]);  ga[3]  = fmaf(xk, wA.w, ga[3]);
                    ga[4]  = fmaf(xk, wB.x, ga[4]);  ga[5]  = fmaf(xk, wB.y, ga[5]);
                    ga[6]  = fmaf(xk, wB.z, ga[6]);  ga[7]  = fmaf(xk, wB.w, ga[7]);
                    ga[8]  = fmaf(xk, wC.x, ga[8]);  ga[9]  = fmaf(xk, wC.y, ga[9]);
                    ga[10] = fmaf(xk, wC.z, ga[10]); ga[11] = fmaf(xk, wC.w, ga[11]);
                    ga[12] = fmaf(xk, wD.x, ga[12]); ga[13] = fmaf(xk, wD.y, ga[13]);
                    ga[14] = fmaf(xk, wD.z, ga[14]); ga[15] = fmaf(xk, wD.w, ga[15]);
                }
            }
            #pragma unroll
            for (int i = 0; i < 16; i++) {
                float xg = ga[i];
                ga[i] = 0.5f * xg * (1.0f + erff(xg * 0.70710678118f));
            }
            float* gp = b2f + t * 128 + g * 16;
            ((float4*)gp)[0] = make_float4(ga[0], ga[1], ga[2], ga[3]);
            ((float4*)gp)[1] = make_float4(ga[4], ga[5], ga[6], ga[7]);
            ((float4*)gp)[2] = make_float4(ga[8], ga[9], ga[10], ga[11]);
            ((float4*)gp)[3] = make_float4(ga[12], ga[13], ga[14], ga[15]);
        }
        __syncwarp();

        // ---- FF2 + residual + LN2 + token mean ----
        {
            float f[8];
            #pragma unroll
            for (int i = 0; i < 8; i++) f[i] = b2S[g * 8 + i];
            const float* grow = b2f + t * 128;
            for (int k4 = 0; k4 < 32; k4++) {
                float4 gv = ((const float4*)grow)[k4];
                #pragma unroll
                for (int kk = 0; kk < 4; kk++) {
                    const float4* wr = (const float4*)(W2S + (k4 * 4 + kk) * 68 + g * 8);
                    float4 wA = wr[0], wB = wr[1];
                    float gk = kk == 0 ? gv.x : kk == 1 ? gv.y : kk == 2 ? gv.z : gv.w;
                    f[0] = fmaf(gk, wA.x, f[0]); f[1] = fmaf(gk, wA.y, f[1]);
                    f[2] = fmaf(gk, wA.z, f[2]); f[3] = fmaf(gk, wA.w, f[3]);
                    f[4] = fmaf(gk, wB.x, f[4]); f[5] = fmaf(gk, wB.y, f[5]);
                    f[6] = fmaf(gk, wB.z, f[6]); f[7] = fmaf(gk, wB.w, f[7]);
                }
            }
            float4 rs0 = ((const float4*)srow)[g*2], rs1 = ((const float4*)srow)[g*2+1];
            f[0] += rs0.x; f[1] += rs0.y; f[2] += rs0.z; f[3] += rs0.w;
            f[4] += rs1.x; f[5] += rs1.y; f[6] += rs1.z; f[7] += rs1.w;
            float sum = 0.f;
            #pragma unroll
            for (int i = 0; i < 8; i++) sum += f[i];
            sum += __shfl_xor_sync(0xffffffffu, sum, 1);
            sum += __shfl_xor_sync(0xffffffffu, sum, 2);
            sum += __shfl_xor_sync(0xffffffffu, sum, 4);
            float mean = sum * 0.015625f;
            float sq = 0.f;
            #pragma unroll
            for (int i = 0; i < 8; i++) { float dd = f[i] - mean; sq = fmaf(dd, dd, sq); }
            sq += __shfl_xor_sync(0xffffffffu, sq, 1);
            sq += __shfl_xor_sync(0xffffffffu, sq, 2);
            sq += __shfl_xor_sync(0xffffffffu, sq, 4);
            float inv = rsqrtf(sq * 0.015625f + 1e-5f);
            #pragma unroll
            for (int i = 0; i < 8; i++) {
                int j = g * 8 + i;
                float x2 = (f[i] - mean) * inv * ln2wS[j] + ln2bS[j];
                x2 += __shfl_xor_sync(0xffffffffu, x2, 8);
                x2 += __shfl_xor_sync(0xffffffffu, x2, 16);
                if (t == 0) hb[j] = x2 * 0.25f;
            }
        }
        __syncwarp();

        // ---- classifier ----
        {
            float o0 = bclsS[l];
            float o1 = bclsS[32 + (l & 7)];
            #pragma unroll 4
            for (int k4 = 0; k4 < 16; k4++) {
                float4 hv = ((const float4*)hb)[k4];
                const float* wr = WclsS + k4 * 160;
                o0 = fmaf(hv.x, wr[l], o0);        o1 = fmaf(hv.x, wr[32 + (l & 7)], o1);
                o0 = fmaf(hv.y, wr[40 + l], o0);   o1 = fmaf(hv.y, wr[72 + (l & 7)], o1);
                o0 = fmaf(hv.z, wr[80 + l], o0);   o1 = fmaf(hv.z, wr[112 + (l & 7)], o1);
                o0 = fmaf(hv.w, wr[120 + l], o0);  o1 = fmaf(hv.w, wr[152 + (l & 7)], o1);
            }
            out[(size_t)n * 40 + l] = o0;
            if (l < 8) out[(size_t)n * 40 + 32 + l] = o1;
        }
        __syncwarp();
    }
}

extern "C" void kernel_launch(void* const* d_in, const int* in_sizes, int n_in,
                              void* d_out, int out_size) {
    const float* x     = (const float*)d_in[0];
    const int*   ei    = (const int*)d_in[1];
    const float* W_in  = (const float*)d_in[2];
    const float* b_in  = (const float*)d_in[3];
    const float* sg_W  = (const float*)d_in[4];
    const float* sg_b  = (const float*)d_in[5];
    const float* inW   = (const float*)d_in[6];
    const float* inb   = (const float*)d_in[7];
    const float* Wout  = (const float*)d_in[8];
    const float* bout  = (const float*)d_in[9];
    const float* W1    = (const float*)d_in[10];
    const float* b1    = (const float*)d_in[11];
    const float* W2    = (const float*)d_in[12];
    const float* b2    = (const float*)d_in[13];
    const float* ln1w  = (const float*)d_in[14];
    const float* ln1b  = (const float*)d_in[15];
    const float* ln2w  = (const float*)d_in[16];
    const float* ln2b  = (const float*)d_in[17];
    const float* Wcls  = (const float*)d_in[18];
    const float* bcls  = (const float*)d_in[19];
    float* out = (float*)d_out;

    cudaFuncSetAttribute(k_in_linear, cudaFuncAttributeMaxDynamicSharedMemorySize, 99584);
    cudaFuncSetAttribute(k_former,    cudaFuncAttributeMaxDynamicSharedMemorySize, 186784);

    // CSR build + dinv
    k_init<<<(Nn + 255) / 256, 256>>>();
    k_count<<<(Ee + 255) / 256, 256>>>(ei + Ee);
    k_scan1<<<NB_SCAN, 1024>>>();
    k_scan2<<<1, 1>>>();
    k_scan3<<<NB_SCAN, 1024>>>();
    k_fill<<<(Ee + 255) / 256, 256>>>(ei, ei + Ee);

    // h0 + seq slot 0
    k_in_linear<<<592, 256, 99584>>>(x, W_in, b_in);

    // folded attention matrices
    k_pre<<<16, 256>>>(inW, inb, Wout, bout);

    // 3 hops: buffers 0 -> 1 -> 2 -> 1, fused gather+token
    const int ib[3] = {0, 1, 2};
    const int ob[3] = {1, 2, 1};
    for (int hop = 0; hop < 3; hop++) {
        k_prop<<<1184, 256>>>(ib[hop], ob[hop], sg_W + hop * 4096, sg_b + hop * 64, hop + 1);
    }

    // fused transformer + pooling + classifier
    k_former<<<148, 512, 186784>>>(W1, b1, W2, b2, ln1w, ln1b, ln2w, ln2b, Wcls, bcls, out);
}